// round 6
// baseline (speedup 1.0000x reference)
#include <cuda_runtime.h>
#include <cstdint>

// ============================================================================
// CRF token loss (ModernBertTokenCRF): B=512, T=2048, L=37
// loss = -( sum_b [num_b - denom_b] ) / n_tok
//
// Forward pass in linear domain: q_t[j] = exp(emit_t[j]) * sum_i q_{t-1}[i]*M[i,j]
// with M = exp(trans); exact power-of-2 renorm folded into the emission factor
// (off the critical path).
//
// R5: LDS.128 q broadcast (10 loads, zero repack), renorm off-path, early qold,
// minimal chain epilogue. 2 warps per batch + per-batch named barrier.
// ============================================================================

#define LSTATE  37
#define TLEN    2048
#define BATCH   512
#define MSTRIDE 40      // padded i-dim: 20 pairs, pairs 19 = (0,0)
#define IPAIRS  20
#define QBUF    40
#define PF      8
#define FULLMASK 0xffffffffu

__device__ __align__(16) float g_MexpT[LSTATE * MSTRIDE]; // [j][i]=exp(trans[i][j])
__device__ float g_num[BATCH];
__device__ float g_denom[BATCH];
__device__ int   g_msum[BATCH];
__device__ int   g_done;

// ---- f32x2 helpers ---------------------------------------------------------
__device__ __forceinline__ void fma2(unsigned long long& acc,
                                     unsigned long long a, unsigned long long b) {
    asm("fma.rn.f32x2 %0, %1, %2, %0;" : "+l"(acc) : "l"(a), "l"(b));
}
__device__ __forceinline__ unsigned long long add2(unsigned long long a,
                                                   unsigned long long b) {
    unsigned long long c;
    asm("add.rn.f32x2 %0, %1, %2;" : "=l"(c) : "l"(a), "l"(b));
    return c;
}
__device__ __forceinline__ float lo32(unsigned long long v) {
    return __uint_as_float((unsigned)v);
}
__device__ __forceinline__ float hi32(unsigned long long v) {
    return __uint_as_float((unsigned)(v >> 32));
}

// ---------------------------------------------------------------------------
// Kernel 1: numerator per batch (one warp each) + prep (block 0)
// ---------------------------------------------------------------------------
__global__ void num_kernel(const float* __restrict__ em,
                           const float* __restrict__ trans,
                           const float* __restrict__ startt,
                           const float* __restrict__ endt,
                           const int*   __restrict__ labels,
                           const int*   __restrict__ mask) {
    if (blockIdx.x == 0) {
        for (int x = threadIdx.x; x < LSTATE * MSTRIDE; x += blockDim.x) {
            int j = x / MSTRIDE, i = x % MSTRIDE;
            g_MexpT[x] = (i < LSTATE) ? expf(trans[i * LSTATE + j]) : 0.0f;
        }
        if (threadIdx.x == 0) g_done = 0;
    }

    int wid  = threadIdx.x >> 5;
    int lane = threadIdx.x & 31;
    int b = blockIdx.x * (blockDim.x >> 5) + wid;
    if (b >= BATCH) return;

    const int*   lb = labels + (size_t)b * TLEN;
    const int*   mk = mask   + (size_t)b * TLEN;
    const float* eb = em     + (size_t)b * TLEN * LSTATE;

    float acc = 0.0f;
    int   msum = 0;
    for (int t = lane; t < TLEN; t += 32) {
        int lt = lb[t];
        int m  = mk[t];
        msum += m;
        if (t == 0) {
            acc += startt[lt] + eb[lt];
        } else if (m) {
            int lp = lb[t - 1];
            acc += trans[lp * LSTATE + lt] + eb[(size_t)t * LSTATE + lt];
        }
    }
    #pragma unroll
    for (int o = 16; o; o >>= 1) {
        acc  += __shfl_down_sync(FULLMASK, acc,  o);
        msum += __shfl_down_sync(FULLMASK, msum, o);
    }
    if (lane == 0) {
        int last = lb[msum - 1];
        g_num[b]  = acc + endt[last];
        g_msum[b] = msum;
    }
}

// ---------------------------------------------------------------------------
// Kernel 2: forward recurrence, 2 warps per batch, + fused final reduction
// ---------------------------------------------------------------------------
__global__ void __launch_bounds__(256, 1)
fwd_kernel(const float* __restrict__ em,
           const float* __restrict__ startt,
           const float* __restrict__ endt,
           const int*   __restrict__ mask,
           float* __restrict__ out) {
    __shared__ __align__(16) float q_sm[4][2][QBUF];  // [batch-in-block][buf][state]
    __shared__ float r_part[4][2];
    __shared__ float r_acc[8];
    __shared__ int   r_nt[8];
    __shared__ int   isLast;

    int tid  = threadIdx.x;
    int lane = tid & 31;
    int wid  = tid >> 5;           // 0..7
    int g    = wid >> 1;           // batch within block: 0..3
    int w    = wid & 1;            // warp within batch: 0 or 1
    int b    = blockIdx.x * 4 + g;
    int barid = 1 + g;             // named barrier id per batch

    const float* eb = em   + (size_t)b * TLEN * LSTATE;
    const int*   mk = mask + (size_t)b * TLEN;

    // columns: warp0 -> 0..18 (lane<19), warp1 -> 19..36 (lane<18)
    int  col    = w ? (19 + lane) : lane;
    bool active = w ? (lane < 18) : (lane < 19);
    int  colc   = (col < LSTATE) ? col : (LSTATE - 1);

    // M column as 20 i-pairs (pair 19 is zero padding)
    unsigned long long Mp[IPAIRS];
    {
        const unsigned long long* cp =
            (const unsigned long long*)(g_MexpT + colc * MSTRIDE);
        #pragma unroll
        for (int k = 0; k < IPAIRS; k++) Mp[k] = cp[k];
    }

    float* buf0 = &q_sm[g][0][0];
    float* buf1 = &q_sm[g][1][0];

    // zero pad slots (37..39) once in both buffers
    if (w == 0 && lane >= 19 && lane < 22) {
        buf0[18 + lane] = 0.0f;
        buf1[18 + lane] = 0.0f;
    }

    // t = 0 init into buf0
    if (active) buf0[col] = __expf(startt[col] + eb[col]);

    // prime prefetch pipeline (steps t=1..PF); exp precomputed here
    float ep[PF];
    int   mp[PF];
    #pragma unroll
    for (int d = 0; d < PF; d++) {
        int tt = 1 + d;
        ep[d] = __expf(eb[(size_t)tt * LSTATE + colc]);
        mp[d] = mk[tt];
    }

    int ktot = 0;
    __syncthreads();

    // steps t = 1..TLEN (t=TLEN is a dummy masked step; TLEN % PF == 0)
    for (int t0 = 1; t0 <= TLEN; t0 += PF) {
        #pragma unroll
        for (int u = 0; u < PF; u++) {
            float ev   = ep[u];
            int   mcur = mp[u];
            // refill prefetch for t + PF (off critical path)
            {
                int t   = t0 + u;
                int tp  = t + PF;
                int tpc = (tp < TLEN) ? tp : (TLEN - 1);
                ep[u] = __expf(eb[(size_t)tpc * LSTATE + colc]);
                mp[u] = (tp < TLEN) ? mk[tp] : 0;
            }

            // u even -> t odd -> read buf0, write buf1 (compile-time select)
            float* bufr = (u & 1) ? buf1 : buf0;
            float* bufw = (u & 1) ? buf0 : buf1;

            asm volatile("bar.sync %0, %1;" :: "r"(barid), "r"(64) : "memory");

            const ulonglong2* q16 = (const ulonglong2*)bufr;
            ulonglong2 p0 = q16[0];
            float qold = bufr[colc];            // early, off-path

            unsigned long long a0 = 0, a1 = 0, a2 = 0, a3 = 0;
            fma2(a0, p0.x, Mp[0]);
            fma2(a1, p0.y, Mp[1]);
            #pragma unroll
            for (int k = 1; k < IPAIRS / 2; k++) {
                ulonglong2 p = q16[k];
                if (k & 1) { fma2(a2, p.x, Mp[2 * k]); fma2(a3, p.y, Mp[2 * k + 1]); }
                else       { fma2(a0, p.x, Mp[2 * k]); fma2(a1, p.y, Mp[2 * k + 1]); }
            }

            // renorm factors off-path: scale from q0's exponent
            float q0 = lo32(p0.x);
            unsigned ebits = (__float_as_uint(q0) >> 23) & 0xffu;
            float scale = __uint_as_float((254u - ebits) << 23);  // 2^-(e-127)
            ktot += (int)ebits - 127;
            float evs   = ev * scale;
            float qolds = qold * scale;

            unsigned long long ac = add2(add2(a0, a1), add2(a2, a3));
            float s  = lo32(ac) + hi32(ac);
            float qn = mcur ? s * evs : qolds;
            if (active) bufw[col] = qn;
        }
    }
    asm volatile("bar.sync %0, %1;" :: "r"(barid), "r"(64) : "memory");

    // final state in buf0 (t=TLEN even): sum_j q[j]*exp(end_j)
    {
        float v = active ? buf0[colc] * __expf(endt[colc]) : 0.0f;
        #pragma unroll
        for (int o = 16; o; o >>= 1) v += __shfl_down_sync(FULLMASK, v, o);
        if (lane == 0) r_part[g][w] = v;
    }
    asm volatile("bar.sync %0, %1;" :: "r"(barid), "r"(64) : "memory");
    if (w == 0 && lane == 0) {
        float ssum = r_part[g][0] + r_part[g][1];
        g_denom[b] = (float)((double)ktot * 0.6931471805599453) + logf(ssum);
    }

    // ---- fused finish: last block reduces everything ----
    __threadfence();
    __syncthreads();
    if (tid == 0)
        isLast = (atomicAdd(&g_done, 1) == (int)gridDim.x - 1);
    __syncthreads();

    if (isLast) {
        __threadfence();
        float acc = 0.0f;
        int   nt  = 0;
        for (int i = tid; i < BATCH; i += 256) {
            acc += g_num[i] - g_denom[i];
            nt  += g_msum[i];
        }
        #pragma unroll
        for (int o = 16; o; o >>= 1) {
            acc += __shfl_down_sync(FULLMASK, acc, o);
            nt  += __shfl_down_sync(FULLMASK, nt,  o);
        }
        if (lane == 0) { r_acc[wid] = acc; r_nt[wid] = nt; }
        __syncthreads();
        if (tid == 0) {
            float tot = 0.0f; int n = 0;
            #pragma unroll
            for (int k = 0; k < 8; k++) { tot += r_acc[k]; n += r_nt[k]; }
            if (n < 1) n = 1;
            out[0] = -tot / (float)n;
        }
    }
}

// ---------------------------------------------------------------------------
// Launch
// ---------------------------------------------------------------------------
extern "C" void kernel_launch(void* const* d_in, const int* in_sizes, int n_in,
                              void* d_out, int out_size) {
    const float* em     = (const float*)d_in[0];   // emissions [512,2048,37]
    const float* trans  = (const float*)d_in[1];   // transitions [37,37]
    const float* startt = (const float*)d_in[2];   // start_transitions [37]
    const float* endt   = (const float*)d_in[3];   // end_transitions [37]
    const int*   labels = (const int*)d_in[4];     // labels [512,2048]
    const int*   mask   = (const int*)d_in[5];     // attention_mask [512,2048]

    num_kernel<<<64, 256>>>(em, trans, startt, endt, labels, mask);
    fwd_kernel<<<BATCH / 4, 256>>>(em, startt, endt, mask, (float*)d_out);
}

// round 7
// speedup vs baseline: 1.0092x; 1.0092x over previous
#include <cuda_runtime.h>
#include <cstdint>

// ============================================================================
// CRF token loss (ModernBertTokenCRF): B=512, T=2048, L=37
// loss = -( sum_b [num_b - denom_b] ) / n_tok
//
// Forward pass in linear domain: q_t[j] = exp(emit_t[j]) * sum_i q_{t-1}[i]*M[i,j]
// with M = exp(trans); exact power-of-2 renorm folded into the emission factor
// (off the critical path).
//
// R5: LDS.128 q broadcast (10 loads, zero repack), renorm off-path, early qold,
// minimal chain epilogue. 2 warps per batch + per-batch named barrier.
// ============================================================================

#define LSTATE  37
#define TLEN    2048
#define BATCH   512
#define MSTRIDE 40      // padded i-dim: 20 pairs, pairs 19 = (0,0)
#define IPAIRS  20
#define QBUF    40
#define PF      8
#define FULLMASK 0xffffffffu

__device__ __align__(16) float g_MexpT[LSTATE * MSTRIDE]; // [j][i]=exp(trans[i][j])
__device__ float g_num[BATCH];
__device__ float g_denom[BATCH];
__device__ int   g_msum[BATCH];
__device__ int   g_done;

// ---- f32x2 helpers ---------------------------------------------------------
__device__ __forceinline__ void fma2(unsigned long long& acc,
                                     unsigned long long a, unsigned long long b) {
    asm("fma.rn.f32x2 %0, %1, %2, %0;" : "+l"(acc) : "l"(a), "l"(b));
}
__device__ __forceinline__ unsigned long long add2(unsigned long long a,
                                                   unsigned long long b) {
    unsigned long long c;
    asm("add.rn.f32x2 %0, %1, %2;" : "=l"(c) : "l"(a), "l"(b));
    return c;
}
__device__ __forceinline__ float lo32(unsigned long long v) {
    return __uint_as_float((unsigned)v);
}
__device__ __forceinline__ float hi32(unsigned long long v) {
    return __uint_as_float((unsigned)(v >> 32));
}

// ---------------------------------------------------------------------------
// Kernel 1: numerator per batch (one warp each) + prep (block 0)
// ---------------------------------------------------------------------------
__global__ void num_kernel(const float* __restrict__ em,
                           const float* __restrict__ trans,
                           const float* __restrict__ startt,
                           const float* __restrict__ endt,
                           const int*   __restrict__ labels,
                           const int*   __restrict__ mask) {
    if (blockIdx.x == 0) {
        for (int x = threadIdx.x; x < LSTATE * MSTRIDE; x += blockDim.x) {
            int j = x / MSTRIDE, i = x % MSTRIDE;
            g_MexpT[x] = (i < LSTATE) ? expf(trans[i * LSTATE + j]) : 0.0f;
        }
        if (threadIdx.x == 0) g_done = 0;
    }

    int wid  = threadIdx.x >> 5;
    int lane = threadIdx.x & 31;
    int b = blockIdx.x * (blockDim.x >> 5) + wid;
    if (b >= BATCH) return;

    const int*   lb = labels + (size_t)b * TLEN;
    const int*   mk = mask   + (size_t)b * TLEN;
    const float* eb = em     + (size_t)b * TLEN * LSTATE;

    float acc = 0.0f;
    int   msum = 0;
    for (int t = lane; t < TLEN; t += 32) {
        int lt = lb[t];
        int m  = mk[t];
        msum += m;
        if (t == 0) {
            acc += startt[lt] + eb[lt];
        } else if (m) {
            int lp = lb[t - 1];
            acc += trans[lp * LSTATE + lt] + eb[(size_t)t * LSTATE + lt];
        }
    }
    #pragma unroll
    for (int o = 16; o; o >>= 1) {
        acc  += __shfl_down_sync(FULLMASK, acc,  o);
        msum += __shfl_down_sync(FULLMASK, msum, o);
    }
    if (lane == 0) {
        int last = lb[msum - 1];
        g_num[b]  = acc + endt[last];
        g_msum[b] = msum;
    }
}

// ---------------------------------------------------------------------------
// Kernel 2: forward recurrence, 2 warps per batch, + fused final reduction
// ---------------------------------------------------------------------------
__global__ void __launch_bounds__(256, 1)
fwd_kernel(const float* __restrict__ em,
           const float* __restrict__ startt,
           const float* __restrict__ endt,
           const int*   __restrict__ mask,
           float* __restrict__ out) {
    __shared__ __align__(16) float q_sm[4][2][QBUF];  // [batch-in-block][buf][state]
    __shared__ float r_part[4][2];
    __shared__ float r_acc[8];
    __shared__ int   r_nt[8];
    __shared__ int   isLast;

    int tid  = threadIdx.x;
    int lane = tid & 31;
    int wid  = tid >> 5;           // 0..7
    int g    = wid >> 1;           // batch within block: 0..3
    int w    = wid & 1;            // warp within batch: 0 or 1
    int b    = blockIdx.x * 4 + g;
    int barid = 1 + g;             // named barrier id per batch

    const float* eb = em   + (size_t)b * TLEN * LSTATE;
    const int*   mk = mask + (size_t)b * TLEN;

    // columns: warp0 -> 0..18 (lane<19), warp1 -> 19..36 (lane<18)
    int  col    = w ? (19 + lane) : lane;
    bool active = w ? (lane < 18) : (lane < 19);
    int  colc   = (col < LSTATE) ? col : (LSTATE - 1);

    // M column as 20 i-pairs (pair 19 is zero padding)
    unsigned long long Mp[IPAIRS];
    {
        const unsigned long long* cp =
            (const unsigned long long*)(g_MexpT + colc * MSTRIDE);
        #pragma unroll
        for (int k = 0; k < IPAIRS; k++) Mp[k] = cp[k];
    }

    float* buf0 = &q_sm[g][0][0];
    float* buf1 = &q_sm[g][1][0];

    // zero pad slots (37..39) once in both buffers
    if (w == 0 && lane >= 19 && lane < 22) {
        buf0[18 + lane] = 0.0f;
        buf1[18 + lane] = 0.0f;
    }

    // t = 0 init into buf0
    if (active) buf0[col] = __expf(startt[col] + eb[col]);

    // prime prefetch pipeline (steps t=1..PF); exp precomputed here
    float ep[PF];
    int   mp[PF];
    #pragma unroll
    for (int d = 0; d < PF; d++) {
        int tt = 1 + d;
        ep[d] = __expf(eb[(size_t)tt * LSTATE + colc]);
        mp[d] = mk[tt];
    }

    int ktot = 0;
    __syncthreads();

    // steps t = 1..TLEN (t=TLEN is a dummy masked step; TLEN % PF == 0)
    for (int t0 = 1; t0 <= TLEN; t0 += PF) {
        #pragma unroll
        for (int u = 0; u < PF; u++) {
            float ev   = ep[u];
            int   mcur = mp[u];
            // refill prefetch for t + PF (off critical path)
            {
                int t   = t0 + u;
                int tp  = t + PF;
                int tpc = (tp < TLEN) ? tp : (TLEN - 1);
                ep[u] = __expf(eb[(size_t)tpc * LSTATE + colc]);
                mp[u] = (tp < TLEN) ? mk[tp] : 0;
            }

            // u even -> t odd -> read buf0, write buf1 (compile-time select)
            float* bufr = (u & 1) ? buf1 : buf0;
            float* bufw = (u & 1) ? buf0 : buf1;

            asm volatile("bar.sync %0, %1;" :: "r"(barid), "r"(64) : "memory");

            const ulonglong2* q16 = (const ulonglong2*)bufr;
            ulonglong2 p0 = q16[0];
            float qold = bufr[colc];            // early, off-path

            unsigned long long a0 = 0, a1 = 0, a2 = 0, a3 = 0;
            fma2(a0, p0.x, Mp[0]);
            fma2(a1, p0.y, Mp[1]);
            #pragma unroll
            for (int k = 1; k < IPAIRS / 2; k++) {
                ulonglong2 p = q16[k];
                if (k & 1) { fma2(a2, p.x, Mp[2 * k]); fma2(a3, p.y, Mp[2 * k + 1]); }
                else       { fma2(a0, p.x, Mp[2 * k]); fma2(a1, p.y, Mp[2 * k + 1]); }
            }

            // renorm factors off-path: scale from q0's exponent
            float q0 = lo32(p0.x);
            unsigned ebits = (__float_as_uint(q0) >> 23) & 0xffu;
            float scale = __uint_as_float((254u - ebits) << 23);  // 2^-(e-127)
            ktot += (int)ebits - 127;
            float evs   = ev * scale;
            float qolds = qold * scale;

            unsigned long long ac = add2(add2(a0, a1), add2(a2, a3));
            float s  = lo32(ac) + hi32(ac);
            float qn = mcur ? s * evs : qolds;
            if (active) bufw[col] = qn;
        }
    }
    asm volatile("bar.sync %0, %1;" :: "r"(barid), "r"(64) : "memory");

    // final state in buf0 (t=TLEN even): sum_j q[j]*exp(end_j)
    {
        float v = active ? buf0[colc] * __expf(endt[colc]) : 0.0f;
        #pragma unroll
        for (int o = 16; o; o >>= 1) v += __shfl_down_sync(FULLMASK, v, o);
        if (lane == 0) r_part[g][w] = v;
    }
    asm volatile("bar.sync %0, %1;" :: "r"(barid), "r"(64) : "memory");
    if (w == 0 && lane == 0) {
        float ssum = r_part[g][0] + r_part[g][1];
        g_denom[b] = (float)((double)ktot * 0.6931471805599453) + logf(ssum);
    }

    // ---- fused finish: last block reduces everything ----
    __threadfence();
    __syncthreads();
    if (tid == 0)
        isLast = (atomicAdd(&g_done, 1) == (int)gridDim.x - 1);
    __syncthreads();

    if (isLast) {
        __threadfence();
        float acc = 0.0f;
        int   nt  = 0;
        for (int i = tid; i < BATCH; i += 256) {
            acc += g_num[i] - g_denom[i];
            nt  += g_msum[i];
        }
        #pragma unroll
        for (int o = 16; o; o >>= 1) {
            acc += __shfl_down_sync(FULLMASK, acc, o);
            nt  += __shfl_down_sync(FULLMASK, nt,  o);
        }
        if (lane == 0) { r_acc[wid] = acc; r_nt[wid] = nt; }
        __syncthreads();
        if (tid == 0) {
            float tot = 0.0f; int n = 0;
            #pragma unroll
            for (int k = 0; k < 8; k++) { tot += r_acc[k]; n += r_nt[k]; }
            if (n < 1) n = 1;
            out[0] = -tot / (float)n;
        }
    }
}

// ---------------------------------------------------------------------------
// Launch
// ---------------------------------------------------------------------------
extern "C" void kernel_launch(void* const* d_in, const int* in_sizes, int n_in,
                              void* d_out, int out_size) {
    const float* em     = (const float*)d_in[0];   // emissions [512,2048,37]
    const float* trans  = (const float*)d_in[1];   // transitions [37,37]
    const float* startt = (const float*)d_in[2];   // start_transitions [37]
    const float* endt   = (const float*)d_in[3];   // end_transitions [37]
    const int*   labels = (const int*)d_in[4];     // labels [512,2048]
    const int*   mask   = (const int*)d_in[5];     // attention_mask [512,2048]

    num_kernel<<<64, 256>>>(em, trans, startt, endt, labels, mask);
    fwd_kernel<<<BATCH / 4, 256>>>(em, startt, endt, mask, (float*)d_out);
}